// round 6
// baseline (speedup 1.0000x reference)
#include <cuda_runtime.h>
#include <math_constants.h>
#include <cstdint>

#define N_PTS 16384
#define C_DIM 64
#define K_NN  16
#define QB    128
#define DB    128
#define NTILE (N_PTS / DB)      // 128
#define NT    256               // threads per knn CTA (8 warps)
#define STR   68                // smem row stride in floats (bank = 4*row+col)

// dynamic smem layout (floats)
#define OFF_QSH 0
#define OFF_QSL (QB * STR)                 // 8704
#define OFF_DB  (2 * QB * STR)             // 17408 ; db[buf][term] term-major inside buf
#define OFF_SQD (OFF_DB + 4 * DB * STR)    // 52224
#define SMEM_FLOATS (OFF_SQD + 2 * DB)     // 52480
#define SMEM_DYN (SMEM_FLOATS * 4)         // 209920 bytes

// Scratch (device globals; no dynamic allocation allowed)
__device__ float g_sq[N_PTS];
__device__ uint4 g_hi4[N_PTS * (C_DIM / 4)];    // tf32 hi bits of x
__device__ uint4 g_lo4[N_PTS * (C_DIM / 4)];    // tf32 residual bits of x
__device__ float g_pd[4 * N_PTS * K_NN];        // per-lane-quarter partial top-k dist
__device__ int   g_pi[4 * N_PTS * K_NN];        // per-lane-quarter partial top-k idx
__device__ int   g_knn[N_PTS * K_NN];
__device__ float g_A[N_PTS * 256];              // x@(W1-W2)+b
__device__ float g_B[N_PTS * 256];              // x@W2

// ---------------- helpers ----------------
static __device__ __forceinline__ uint32_t smem_u32(const void* p) {
    uint32_t a;
    asm("{ .reg .u64 t; cvta.to.shared.u64 t, %1; cvt.u32.u64 %0, t; }"
        : "=r"(a) : "l"(p));
    return a;
}
static __device__ __forceinline__ uint32_t tf32bits(float v) {
    uint32_t r;
    asm("cvt.rna.tf32.f32 %0, %1;" : "=r"(r) : "f"(v));
    return r;
}
static __device__ __forceinline__ void cp16(uint32_t dst, const void* src) {
    asm volatile("cp.async.cg.shared.global [%0], [%1], 16;" :: "r"(dst), "l"(src));
}
static __device__ __forceinline__ void mma_tf32(float* cc,
        uint32_t a0, uint32_t a1, uint32_t a2, uint32_t a3,
        uint32_t b0, uint32_t b1) {
    asm volatile("mma.sync.aligned.m16n8k8.row.col.f32.tf32.tf32.f32 "
                 "{%0,%1,%2,%3}, {%4,%5,%6,%7}, {%8,%9}, {%0,%1,%2,%3};"
                 : "+f"(cc[0]), "+f"(cc[1]), "+f"(cc[2]), "+f"(cc[3])
                 : "r"(a0), "r"(a1), "r"(a2), "r"(a3), "r"(b0), "r"(b1));
}
// lexicographic (d, idx) insertion — matches jax top_k tie-breaking (lower idx wins)
static __device__ __forceinline__ void ins_lex(float d, int i,
                                               float (&kd)[K_NN], int (&ki)[K_NN]) {
    kd[K_NN - 1] = d; ki[K_NN - 1] = i;
#pragma unroll
    for (int t = K_NN - 1; t > 0; --t) {
        bool sw = (kd[t] < kd[t - 1]) ||
                  (kd[t] == kd[t - 1] && ki[t] < ki[t - 1]);
        if (sw) {
            float td = kd[t]; kd[t] = kd[t - 1]; kd[t - 1] = td;
            int ti = ki[t]; ki[t] = ki[t - 1]; ki[t - 1] = ti;
        }
    }
}
static __device__ __forceinline__ void upd(float d, int col, int q,
                                           float (&kd)[K_NN], int (&ki)[K_NN]) {
    if (col != q && (d < kd[K_NN - 1] ||
                     (d == kd[K_NN - 1] && col < ki[K_NN - 1])))
        ins_lex(d, col, kd, ki);
}

// ---------------- 1) squared norms ----------------
__global__ void sqnorm_kernel(const float* __restrict__ x) {
    int i = blockIdx.x * blockDim.x + threadIdx.x;
    const float4* xr = (const float4*)(x + (long)i * C_DIM);
    float s = 0.f;
#pragma unroll
    for (int t = 0; t < C_DIM / 4; ++t) {
        float4 v = xr[t];
        s += v.x * v.x + v.y * v.y + v.z * v.z + v.w * v.w;
    }
    g_sq[i] = s;
}

// ---------------- 2) tf32 hi/lo split of x ----------------
__global__ void split_kernel(const float* __restrict__ x) {
    int i = blockIdx.x * blockDim.x + threadIdx.x;   // uint4 index
    float4 v = ((const float4*)x)[i];
    uint4 h, l;
    h.x = tf32bits(v.x); l.x = tf32bits(v.x - __uint_as_float(h.x));
    h.y = tf32bits(v.y); l.y = tf32bits(v.y - __uint_as_float(h.y));
    h.z = tf32bits(v.z); l.z = tf32bits(v.z - __uint_as_float(h.z));
    h.w = tf32bits(v.w); l.w = tf32bits(v.w - __uint_as_float(h.w));
    g_hi4[i] = h; g_lo4[i] = l;
}

// ---------------- 3) feature GEMMs: A = x@(W1-W2)+b, B = x@W2 ----------------
__global__ void feat_gemm_kernel(const float* __restrict__ x,
                                 const float* __restrict__ W,
                                 const float* __restrict__ b) {
    __shared__ float xs[16][C_DIM];
    int col = threadIdx.x;
    int row0 = blockIdx.x * 16;
    ((float4*)xs)[col] = ((const float4*)(x + (long)row0 * C_DIM))[col];
    __syncthreads();

    float p1[16], p2[16];
#pragma unroll
    for (int r = 0; r < 16; ++r) { p1[r] = 0.f; p2[r] = 0.f; }
#pragma unroll 4
    for (int c = 0; c < C_DIM; ++c) {
        float w1 = __ldg(W + c * 256 + col);
        float w2 = __ldg(W + (C_DIM + c) * 256 + col);
#pragma unroll
        for (int r = 0; r < 16; ++r) {
            float xv = xs[r][c];
            p1[r] = fmaf(xv, w1, p1[r]);
            p2[r] = fmaf(xv, w2, p2[r]);
        }
    }
    float bias = __ldg(b + col);
#pragma unroll
    for (int r = 0; r < 16; ++r) {
        g_A[(long)(row0 + r) * 256 + col] = p1[r] - p2[r] + bias;
        g_B[(long)(row0 + r) * 256 + col] = p2[r];
    }
}

// ---------------- 4) KNN via 3xTF32 mma.sync + fused register top-k ----------------
__global__ void __launch_bounds__(NT, 1) knn_mma_kernel() {
    extern __shared__ float sm[];
    int tid = threadIdx.x;
    int warp = tid >> 5, lane = tid & 31;
    int g = lane >> 2, c = lane & 3;
    int qbase = blockIdx.x * QB;
    int r0 = warp * 16;                 // warp's query m-stripe
    int q0 = qbase + r0 + g, q1 = q0 + 8;

    // ---- fill query tiles (hi/lo, prescaled by -2; exact scaling) ----
#pragma unroll
    for (int it = 0; it < 8; ++it) {
        int idx = it * NT + tid;        // idx = q*16 + j
        int q = idx >> 4, j = idx & 15;
        uint4 h = g_hi4[(long)(qbase + q) * 16 + j];
        uint4 l = g_lo4[(long)(qbase + q) * 16 + j];
        float4 fh, fl;
        fh.x = -2.f * __uint_as_float(h.x); fh.y = -2.f * __uint_as_float(h.y);
        fh.z = -2.f * __uint_as_float(h.z); fh.w = -2.f * __uint_as_float(h.w);
        fl.x = -2.f * __uint_as_float(l.x); fl.y = -2.f * __uint_as_float(l.y);
        fl.z = -2.f * __uint_as_float(l.z); fl.w = -2.f * __uint_as_float(l.w);
        *(float4*)&sm[OFF_QSH + q * STR + j * 4] = fh;
        *(float4*)&sm[OFF_QSL + q * STR + j * 4] = fl;
    }

    float kd0[K_NN], kd1[K_NN];
    int   ki0[K_NN], ki1[K_NN];
#pragma unroll
    for (int t = 0; t < K_NN; ++t) {
        kd0[t] = CUDART_INF_F; ki0[t] = 0x7fffffff;
        kd1[t] = CUDART_INF_F; ki1[t] = 0x7fffffff;
    }

    // ---- db tile fill via cp.async (double buffered) ----
    auto fill_tile = [&](int tile, int buf) {
        int base = tile * DB;
        uint32_t dH = smem_u32(&sm[OFF_DB + buf * (2 * DB * STR)]);
        uint32_t dL = dH + DB * STR * 4;
        const uint4* sH = &g_hi4[(long)base * 16];
        const uint4* sL = &g_lo4[(long)base * 16];
#pragma unroll
        for (int it = 0; it < 8; ++it) {
            int idx = it * NT + tid;    // idx = n*16 + j
            int n = idx >> 4, j = idx & 15;
            uint32_t off = (uint32_t)(n * STR + j * 4) * 4;
            cp16(dH + off, sH + idx);
            cp16(dL + off, sL + idx);
        }
        if (tid < 32)
            cp16(smem_u32(&sm[OFF_SQD + buf * DB + tid * 4]), g_sq + base + tid * 4);
    };

    fill_tile(0, 0);
    asm volatile("cp.async.commit_group;" ::: "memory");
    __syncthreads();                    // qs visible to all warps

    for (int tile = 0; tile < NTILE; ++tile) {
        int buf = tile & 1;
        if (tile + 1 < NTILE) {
            fill_tile(tile + 1, buf ^ 1);
            asm volatile("cp.async.commit_group;" ::: "memory");
            asm volatile("cp.async.wait_group 1;" ::: "memory");
        } else {
            asm volatile("cp.async.wait_group 0;" ::: "memory");
        }
        __syncthreads();

        const float* dbH = &sm[OFF_DB + buf * (2 * DB * STR)];
        const float* dbL = dbH + DB * STR;
        const float* sq = &sm[OFF_SQD + buf * DB];

        float acc[64];
#pragma unroll
        for (int i = 0; i < 64; ++i) acc[i] = 0.f;

#pragma unroll
        for (int kc = 0; kc < 8; ++kc) {
            int kb = kc * 8;
            const float* qh = &sm[OFF_QSH + (r0 + g) * STR + kb + c];
            const float* ql = &sm[OFF_QSL + (r0 + g) * STR + kb + c];
            uint32_t aH0 = *(const uint32_t*)(qh);
            uint32_t aH1 = *(const uint32_t*)(qh + 8 * STR);
            uint32_t aH2 = *(const uint32_t*)(qh + 4);
            uint32_t aH3 = *(const uint32_t*)(qh + 8 * STR + 4);
            uint32_t aL0 = *(const uint32_t*)(ql);
            uint32_t aL1 = *(const uint32_t*)(ql + 8 * STR);
            uint32_t aL2 = *(const uint32_t*)(ql + 4);
            uint32_t aL3 = *(const uint32_t*)(ql + 8 * STR + 4);
            const float* bh = dbH + g * STR + kb + c;
            const float* bl = dbL + g * STR + kb + c;
#pragma unroll
            for (int nf = 0; nf < 16; ++nf) {
                uint32_t bH0 = *(const uint32_t*)(bh + nf * 8 * STR);
                uint32_t bH1 = *(const uint32_t*)(bh + nf * 8 * STR + 4);
                uint32_t bL0 = *(const uint32_t*)(bl + nf * 8 * STR);
                uint32_t bL1 = *(const uint32_t*)(bl + nf * 8 * STR + 4);
                float* cc = acc + nf * 4;
                mma_tf32(cc, aH0, aH1, aH2, aH3, bH0, bH1);   // hi·hi
                mma_tf32(cc, aL0, aL1, aL2, aL3, bH0, bH1);   // lo·hi
                mma_tf32(cc, aH0, aH1, aH2, aH3, bL0, bL1);   // hi·lo
            }
        }

        // ---- epilogue: d = |p|^2 - 2 q·p (sq_q dropped; rank-invariant) ----
        int tb = tile * DB;
#pragma unroll
        for (int nf = 0; nf < 16; ++nf) {
            int col0 = nf * 8 + 2 * c;
            float2 s = *(const float2*)(sq + col0);
            int gc0 = tb + col0, gc1 = gc0 + 1;
            upd(acc[nf * 4 + 0] + s.x, gc0, q0, kd0, ki0);
            upd(acc[nf * 4 + 1] + s.y, gc1, q0, kd0, ki0);
            upd(acc[nf * 4 + 2] + s.x, gc0, q1, kd1, ki1);
            upd(acc[nf * 4 + 3] + s.y, gc1, q1, kd1, ki1);
        }
        __syncthreads();   // all warps done with this buffer before refill
    }

    long ob0 = ((long)c * N_PTS + q0) * K_NN;
    long ob1 = ((long)c * N_PTS + q1) * K_NN;
#pragma unroll
    for (int t = 0; t < K_NN; ++t) {
        g_pd[ob0 + t] = kd0[t]; g_pi[ob0 + t] = ki0[t];
        g_pd[ob1 + t] = kd1[t]; g_pi[ob1 + t] = ki1[t];
    }
}

// ---------------- 5) merge 4 lane-quarter partial lists per query ----------------
__global__ void merge_kernel() {
    int q = blockIdx.x * blockDim.x + threadIdx.x;
    float kd[K_NN];
    int   ki[K_NN];
#pragma unroll
    for (int t = 0; t < K_NN; ++t) { kd[t] = CUDART_INF_F; ki[t] = 0x7fffffff; }
    for (int s = 0; s < 4; ++s) {
        long ob = ((long)s * N_PTS + q) * K_NN;
#pragma unroll
        for (int t2 = 0; t2 < K_NN; ++t2) {
            float d = g_pd[ob + t2];
            int   i = g_pi[ob + t2];
            if (d < kd[K_NN - 1] || (d == kd[K_NN - 1] && i < ki[K_NN - 1]))
                ins_lex(d, i, kd, ki);
        }
    }
#pragma unroll
    for (int t = 0; t < K_NN; ++t) g_knn[(long)q * K_NN + t] = ki[t];
}

// ---------------- 6) gather + max + relu + pixel-shuffle scatter ----------------
__global__ void gather_max_kernel(float* __restrict__ y) {
    int t = threadIdx.x;
    int q = blockIdx.x * 4 + (t >> 6);
    int c = t & 63;
    const int* idx = g_knn + (long)q * K_NN;
    const float4* Bv = (const float4*)g_B;
    float4 m = make_float4(-CUDART_INF_F, -CUDART_INF_F, -CUDART_INF_F, -CUDART_INF_F);
#pragma unroll
    for (int k = 0; k < K_NN; ++k) {
        int j = __ldg(idx + k);
        float4 bv = Bv[(long)j * 64 + c];
        m.x = fmaxf(m.x, bv.x); m.y = fmaxf(m.y, bv.y);
        m.z = fmaxf(m.z, bv.z); m.w = fmaxf(m.w, bv.w);
    }
    float4 a = ((const float4*)g_A)[(long)q * 64 + c];
    y[((long)q * 4 + 0) * 64 + c] = fmaxf(a.x + m.x, 0.f);
    y[((long)q * 4 + 1) * 64 + c] = fmaxf(a.y + m.y, 0.f);
    y[((long)q * 4 + 2) * 64 + c] = fmaxf(a.z + m.z, 0.f);
    y[((long)q * 4 + 3) * 64 + c] = fmaxf(a.w + m.w, 0.f);
}

extern "C" void kernel_launch(void* const* d_in, const int* in_sizes, int n_in,
                              void* d_out, int out_size) {
    const float* x = (const float*)d_in[0];   // (16384, 64) f32
    const float* W = (const float*)d_in[1];   // (128, 256) f32
    const float* b = (const float*)d_in[2];   // (256,) f32
    float* y = (float*)d_out;                 // (65536, 64) f32

    cudaFuncSetAttribute(knn_mma_kernel,
                         cudaFuncAttributeMaxDynamicSharedMemorySize, SMEM_DYN);

    sqnorm_kernel<<<N_PTS / 256, 256>>>(x);
    split_kernel<<<(N_PTS * C_DIM / 4) / 256, 256>>>(x);
    feat_gemm_kernel<<<N_PTS / 16, 256>>>(x, W, b);
    knn_mma_kernel<<<N_PTS / QB, NT, SMEM_DYN>>>();
    merge_kernel<<<N_PTS / 128, 128>>>();
    gather_max_kernel<<<N_PTS / 4, 256>>>(y);
}

// round 8
// speedup vs baseline: 1.8438x; 1.8438x over previous
#include <cuda_runtime.h>
#include <math_constants.h>
#include <cstdint>

#define N_PTS 16384
#define C_DIM 64
#define K_NN  16
#define QB    128
#define DB    64
#define NTILE (N_PTS / DB)      // 256
#define NT    256               // threads per knn CTA (8 warps)
#define STR   68                // smem row stride in floats

// dynamic smem layout (floats)
#define OFF_QSH 0
#define OFF_QSL (QB * STR)                    // 8704
#define OFF_DB  (2 * QB * STR)                // 17408 ; 2 bufs x (hi|lo) x 64*STR
#define OFF_SQD (OFF_DB + 2 * 2 * DB * STR)   // 34816
#define OFF_DST (OFF_SQD + 2 * DB)            // 34944
#define SMEM_FLOATS (OFF_DST + QB * STR)      // 43648
#define SMEM_DYN (SMEM_FLOATS * 4)            // 174592 bytes

// Scratch (device globals; no dynamic allocation allowed)
__device__ float g_sq[N_PTS];
__device__ uint4 g_hi4[N_PTS * (C_DIM / 4)];    // tf32 hi bits of x
__device__ uint4 g_lo4[N_PTS * (C_DIM / 4)];    // tf32 residual bits of x
__device__ int   g_knn[N_PTS * K_NN];
__device__ float g_A[N_PTS * 256];              // x@(W1-W2)+b
__device__ float g_B[N_PTS * 256];              // x@W2

// ---------------- helpers ----------------
static __device__ __forceinline__ uint32_t smem_u32(const void* p) {
    uint32_t a;
    asm("{ .reg .u64 t; cvta.to.shared.u64 t, %1; cvt.u32.u64 %0, t; }"
        : "=r"(a) : "l"(p));
    return a;
}
static __device__ __forceinline__ uint32_t tf32bits(float v) {
    uint32_t r;
    asm("cvt.rna.tf32.f32 %0, %1;" : "=r"(r) : "f"(v));
    return r;
}
static __device__ __forceinline__ void cp16(uint32_t dst, const void* src) {
    asm volatile("cp.async.cg.shared.global [%0], [%1], 16;" :: "r"(dst), "l"(src));
}
static __device__ __forceinline__ void mma_tf32(float* cc,
        uint32_t a0, uint32_t a1, uint32_t a2, uint32_t a3,
        uint32_t b0, uint32_t b1) {
    asm volatile("mma.sync.aligned.m16n8k8.row.col.f32.tf32.tf32.f32 "
                 "{%0,%1,%2,%3}, {%4,%5,%6,%7}, {%8,%9}, {%0,%1,%2,%3};"
                 : "+f"(cc[0]), "+f"(cc[1]), "+f"(cc[2]), "+f"(cc[3])
                 : "r"(a0), "r"(a1), "r"(a2), "r"(a3), "r"(b0), "r"(b1));
}
// lexicographic (d, idx) insertion — matches jax top_k tie-breaking
static __device__ __forceinline__ void ins_lex(float d, int i,
                                               float (&kd)[K_NN], int (&ki)[K_NN]) {
    kd[K_NN - 1] = d; ki[K_NN - 1] = i;
#pragma unroll
    for (int t = K_NN - 1; t > 0; --t) {
        bool sw = (kd[t] < kd[t - 1]) ||
                  (kd[t] == kd[t - 1] && ki[t] < ki[t - 1]);
        if (sw) {
            float td = kd[t]; kd[t] = kd[t - 1]; kd[t - 1] = td;
            int ti = ki[t]; ki[t] = ki[t - 1]; ki[t - 1] = ti;
        }
    }
}

// ---------------- 1) squared norms ----------------
__global__ void sqnorm_kernel(const float* __restrict__ x) {
    int i = blockIdx.x * blockDim.x + threadIdx.x;
    const float4* xr = (const float4*)(x + (long)i * C_DIM);
    float s = 0.f;
#pragma unroll
    for (int t = 0; t < C_DIM / 4; ++t) {
        float4 v = xr[t];
        s += v.x * v.x + v.y * v.y + v.z * v.z + v.w * v.w;
    }
    g_sq[i] = s;
}

// ---------------- 2) tf32 hi/lo split of x ----------------
__global__ void split_kernel(const float* __restrict__ x) {
    int i = blockIdx.x * blockDim.x + threadIdx.x;   // uint4 index
    float4 v = ((const float4*)x)[i];
    uint4 h, l;
    h.x = tf32bits(v.x); l.x = tf32bits(v.x - __uint_as_float(h.x));
    h.y = tf32bits(v.y); l.y = tf32bits(v.y - __uint_as_float(h.y));
    h.z = tf32bits(v.z); l.z = tf32bits(v.z - __uint_as_float(h.z));
    h.w = tf32bits(v.w); l.w = tf32bits(v.w - __uint_as_float(h.w));
    g_hi4[i] = h; g_lo4[i] = l;
}

// ---------------- 3) feature GEMMs: A = x@(W1-W2)+b, B = x@W2 ----------------
__global__ void feat_gemm_kernel(const float* __restrict__ x,
                                 const float* __restrict__ W,
                                 const float* __restrict__ b) {
    __shared__ float xs[16][C_DIM];
    int col = threadIdx.x;
    int row0 = blockIdx.x * 16;
    ((float4*)xs)[col] = ((const float4*)(x + (long)row0 * C_DIM))[col];
    __syncthreads();

    float p1[16], p2[16];
#pragma unroll
    for (int r = 0; r < 16; ++r) { p1[r] = 0.f; p2[r] = 0.f; }
#pragma unroll 4
    for (int c = 0; c < C_DIM; ++c) {
        float w1 = __ldg(W + c * 256 + col);
        float w2 = __ldg(W + (C_DIM + c) * 256 + col);
#pragma unroll
        for (int r = 0; r < 16; ++r) {
            float xv = xs[r][c];
            p1[r] = fmaf(xv, w1, p1[r]);
            p2[r] = fmaf(xv, w2, p2[r]);
        }
    }
    float bias = __ldg(b + col);
#pragma unroll
    for (int r = 0; r < 16; ++r) {
        g_A[(long)(row0 + r) * 256 + col] = p1[r] - p2[r] + bias;
        g_B[(long)(row0 + r) * 256 + col] = p2[r];
    }
}

// ---------------- 4) KNN: 3xTF32 mma.sync -> smem dist tile -> row scan ----------------
__global__ void __launch_bounds__(NT, 1) knn_mma_kernel() {
    extern __shared__ float sm[];
    int tid = threadIdx.x;
    int warp = tid >> 5, lane = tid & 31;
    int g = lane >> 2, c = lane & 3;
    int qbase = blockIdx.x * QB;
    int r0 = warp * 16;                       // warp's query m-stripe

    // ---- fill query tiles (hi/lo, prescaled by -2; exact scaling) ----
#pragma unroll
    for (int it = 0; it < 8; ++it) {
        int idx = it * NT + tid;              // idx = q*16 + j
        int qq = idx >> 4, j = idx & 15;
        uint4 h = g_hi4[(long)(qbase + qq) * 16 + j];
        uint4 l = g_lo4[(long)(qbase + qq) * 16 + j];
        float4 fh, fl;
        fh.x = -2.f * __uint_as_float(h.x); fh.y = -2.f * __uint_as_float(h.y);
        fh.z = -2.f * __uint_as_float(h.z); fh.w = -2.f * __uint_as_float(h.w);
        fl.x = -2.f * __uint_as_float(l.x); fl.y = -2.f * __uint_as_float(l.y);
        fl.z = -2.f * __uint_as_float(l.z); fl.w = -2.f * __uint_as_float(l.w);
        *(float4*)&sm[OFF_QSH + qq * STR + j * 4] = fh;
        *(float4*)&sm[OFF_QSL + qq * STR + j * 4] = fl;
    }

    // db tile fill via cp.async (all 256 threads; 2048 cp16 per tile)
    auto fill_tile = [&](int tile, int buf) {
        int base = tile * DB;
        uint32_t dH = smem_u32(&sm[OFF_DB + buf * (2 * DB * STR)]);
        uint32_t dL = dH + DB * STR * 4;
        const uint4* sH = &g_hi4[(long)base * 16];
        const uint4* sL = &g_lo4[(long)base * 16];
#pragma unroll
        for (int it = 0; it < 4; ++it) {
            int idx = it * NT + tid;          // idx = n*16 + j, 1024 total
            int n = idx >> 4, j = idx & 15;
            uint32_t off = (uint32_t)(n * STR + j * 4) * 4;
            cp16(dH + off, sH + idx);
            cp16(dL + off, sL + idx);
        }
        if (tid < 16)
            cp16(smem_u32(&sm[OFF_SQD + buf * DB + tid * 4]), g_sq + base + tid * 4);
    };

    float kd[K_NN];
    int   ki[K_NN];
#pragma unroll
    for (int t = 0; t < K_NN; ++t) { kd[t] = CUDART_INF_F; ki[t] = 0x7fffffff; }

    fill_tile(0, 0);
    asm volatile("cp.async.commit_group;" ::: "memory");
    asm volatile("cp.async.wait_group 0;" ::: "memory");
    __syncthreads();

    for (int tile = 0; tile < NTILE; ++tile) {
        int buf = tile & 1;
        int tb = tile * DB;
        const float* dbH = &sm[OFF_DB + buf * (2 * DB * STR)];
        const float* dbL = dbH + DB * STR;
        const float* sq = &sm[OFF_SQD + buf * DB];

        // ---- phase A: mma (128q x 64db), all 8 warps ----
        float acc[32];
#pragma unroll
        for (int i = 0; i < 32; ++i) acc[i] = 0.f;

#pragma unroll
        for (int kc = 0; kc < 8; ++kc) {
            int kb = kc * 8;
            const float* qh = &sm[OFF_QSH + (r0 + g) * STR + kb + c];
            const float* ql = &sm[OFF_QSL + (r0 + g) * STR + kb + c];
            uint32_t aH0 = *(const uint32_t*)(qh);
            uint32_t aH1 = *(const uint32_t*)(qh + 8 * STR);
            uint32_t aH2 = *(const uint32_t*)(qh + 4);
            uint32_t aH3 = *(const uint32_t*)(qh + 8 * STR + 4);
            uint32_t aL0 = *(const uint32_t*)(ql);
            uint32_t aL1 = *(const uint32_t*)(ql + 8 * STR);
            uint32_t aL2 = *(const uint32_t*)(ql + 4);
            uint32_t aL3 = *(const uint32_t*)(ql + 8 * STR + 4);
            const float* bh = dbH + g * STR + kb + c;
            const float* bl = dbL + g * STR + kb + c;
#pragma unroll
            for (int nf = 0; nf < 8; ++nf) {
                uint32_t bH0 = *(const uint32_t*)(bh + nf * 8 * STR);
                uint32_t bH1 = *(const uint32_t*)(bh + nf * 8 * STR + 4);
                uint32_t bL0 = *(const uint32_t*)(bl + nf * 8 * STR);
                uint32_t bL1 = *(const uint32_t*)(bl + nf * 8 * STR + 4);
                float* cc = acc + nf * 4;
                mma_tf32(cc, aH0, aH1, aH2, aH3, bH0, bH1);   // hi*hi
                mma_tf32(cc, aL0, aL1, aL2, aL3, bH0, bH1);   // lo*hi
                mma_tf32(cc, aH0, aH1, aH2, aH3, bL0, bL1);   // hi*lo
            }
        }
        // STS dist (+|p|^2; query norm dropped — rank-invariant)
#pragma unroll
        for (int nf = 0; nf < 8; ++nf) {
            int col0 = nf * 8 + 2 * c;
            float2 s = *(const float2*)(sq + col0);
            float2 v0 = make_float2(acc[nf * 4 + 0] + s.x, acc[nf * 4 + 1] + s.y);
            float2 v1 = make_float2(acc[nf * 4 + 2] + s.x, acc[nf * 4 + 3] + s.y);
            *(float2*)&sm[OFF_DST + (r0 + g) * STR + col0] = v0;
            *(float2*)&sm[OFF_DST + (r0 + g + 8) * STR + col0] = v1;
        }

        // ---- prefetch next tile (overlaps the scan below) ----
        if (tile + 1 < NTILE) {
            fill_tile(tile + 1, buf ^ 1);
            asm volatile("cp.async.commit_group;" ::: "memory");
        }
        __syncthreads();   // dist tile ready

        // ---- phase B: scan (threads 0..127, one query each) ----
        if (tid < QB) {
            int q = qbase + tid;
            int self = q - tb;
            if ((unsigned)self < (unsigned)DB)
                sm[OFF_DST + tid * STR + self] = CUDART_INF_F;
            float thr = kd[K_NN - 1];
            const float* row = &sm[OFF_DST + tid * STR];
#pragma unroll
            for (int j = 0; j < DB / 4; ++j) {
                float4 dv = *(const float4*)(row + 4 * j);
                float mn = fminf(fminf(dv.x, dv.y), fminf(dv.z, dv.w));
                if (mn <= thr) {
                    float ds[4] = {dv.x, dv.y, dv.z, dv.w};
#pragma unroll
                    for (int e = 0; e < 4; ++e) {
                        int col = tb + 4 * j + e;
                        if (ds[e] < thr ||
                            (ds[e] == thr && col < ki[K_NN - 1])) {
                            ins_lex(ds[e], col, kd, ki);
                            thr = kd[K_NN - 1];
                        }
                    }
                }
            }
        }
        asm volatile("cp.async.wait_group 0;" ::: "memory");
        __syncthreads();   // next db buf ready + dist free
    }

    if (tid < QB) {
        int q = qbase + tid;
#pragma unroll
        for (int t = 0; t < K_NN; ++t) g_knn[(long)q * K_NN + t] = ki[t];
    }
}

// ---------------- 5) gather + max + relu + pixel-shuffle scatter ----------------
__global__ void gather_max_kernel(float* __restrict__ y) {
    int t = threadIdx.x;
    int q = blockIdx.x * 4 + (t >> 6);
    int c = t & 63;
    const int* idx = g_knn + (long)q * K_NN;
    const float4* Bv = (const float4*)g_B;
    float4 m = make_float4(-CUDART_INF_F, -CUDART_INF_F, -CUDART_INF_F, -CUDART_INF_F);
#pragma unroll
    for (int k = 0; k < K_NN; ++k) {
        int j = __ldg(idx + k);
        float4 bv = Bv[(long)j * 64 + c];
        m.x = fmaxf(m.x, bv.x); m.y = fmaxf(m.y, bv.y);
        m.z = fmaxf(m.z, bv.z); m.w = fmaxf(m.w, bv.w);
    }
    float4 a = ((const float4*)g_A)[(long)q * 64 + c];
    y[((long)q * 4 + 0) * 64 + c] = fmaxf(a.x + m.x, 0.f);
    y[((long)q * 4 + 1) * 64 + c] = fmaxf(a.y + m.y, 0.f);
    y[((long)q * 4 + 2) * 64 + c] = fmaxf(a.z + m.z, 0.f);
    y[((long)q * 4 + 3) * 64 + c] = fmaxf(a.w + m.w, 0.f);
}

extern "C" void kernel_launch(void* const* d_in, const int* in_sizes, int n_in,
                              void* d_out, int out_size) {
    const float* x = (const float*)d_in[0];   // (16384, 64) f32
    const float* W = (const float*)d_in[1];   // (128, 256) f32
    const float* b = (const float*)d_in[2];   // (256,) f32
    float* y = (float*)d_out;                 // (65536, 64) f32

    cudaFuncSetAttribute(knn_mma_kernel,
                         cudaFuncAttributeMaxDynamicSharedMemorySize, SMEM_DYN);

    sqnorm_kernel<<<N_PTS / 256, 256>>>(x);
    split_kernel<<<(N_PTS * C_DIM / 4) / 256, 256>>>(x);
    feat_gemm_kernel<<<N_PTS / 16, 256>>>(x, W, b);
    knn_mma_kernel<<<N_PTS / QB, NT, SMEM_DYN>>>();
    gather_max_kernel<<<N_PTS / 4, 256>>>(y);
}

// round 9
// speedup vs baseline: 1.9303x; 1.0469x over previous
#include <cuda_runtime.h>
#include <math_constants.h>
#include <cstdint>

#define N_PTS 16384
#define C_DIM 64
#define K_NN  16
#define QB    128
#define DB    64
#define NTILE (N_PTS / DB)      // 256
#define NT    512               // threads per knn CTA (16 warps)
#define STR   68                // smem row stride in floats

// dynamic smem layout (floats)
#define OFF_QSH 0
#define OFF_QSL (QB * STR)                    // 8704
#define OFF_DB  (2 * QB * STR)                // 17408 ; 2 bufs x (hi|lo) x 64*STR
#define OFF_SQD (OFF_DB + 2 * 2 * DB * STR)   // 34816
#define OFF_DST (OFF_SQD + 2 * DB)            // 34944
#define SMEM_FLOATS (OFF_DST + QB * STR)      // 43648
#define SMEM_DYN (SMEM_FLOATS * 4)            // 174592 bytes

// Scratch (device globals; no dynamic allocation allowed)
__device__ float g_sq[N_PTS];
__device__ uint4 g_hi4[N_PTS * (C_DIM / 4)];    // tf32 hi bits of x
__device__ uint4 g_lo4[N_PTS * (C_DIM / 4)];    // tf32 residual bits of x
__device__ int   g_knn[N_PTS * K_NN];
__device__ float g_A[N_PTS * 256];              // x@(W1-W2)+b
__device__ float g_B[N_PTS * 256];              // x@W2

// ---------------- helpers ----------------
static __device__ __forceinline__ uint32_t smem_u32(const void* p) {
    uint32_t a;
    asm("{ .reg .u64 t; cvta.to.shared.u64 t, %1; cvt.u32.u64 %0, t; }"
        : "=r"(a) : "l"(p));
    return a;
}
static __device__ __forceinline__ uint32_t tf32bits(float v) {
    uint32_t r;
    asm("cvt.rna.tf32.f32 %0, %1;" : "=r"(r) : "f"(v));
    return r;
}
static __device__ __forceinline__ void cp16(uint32_t dst, const void* src) {
    asm volatile("cp.async.cg.shared.global [%0], [%1], 16;" :: "r"(dst), "l"(src));
}
// NOT volatile: pure register op; lets ptxas schedule/interleave the MMA stream
static __device__ __forceinline__ void mma_tf32(float* cc,
        uint32_t a0, uint32_t a1, uint32_t a2, uint32_t a3,
        uint32_t b0, uint32_t b1) {
    asm("mma.sync.aligned.m16n8k8.row.col.f32.tf32.tf32.f32 "
        "{%0,%1,%2,%3}, {%4,%5,%6,%7}, {%8,%9}, {%0,%1,%2,%3};"
        : "+f"(cc[0]), "+f"(cc[1]), "+f"(cc[2]), "+f"(cc[3])
        : "r"(a0), "r"(a1), "r"(a2), "r"(a3), "r"(b0), "r"(b1));
}
// lexicographic (d, idx) insertion — matches jax top_k tie-breaking
static __device__ __forceinline__ void ins_lex(float d, int i,
                                               float (&kd)[K_NN], int (&ki)[K_NN]) {
    kd[K_NN - 1] = d; ki[K_NN - 1] = i;
#pragma unroll
    for (int t = K_NN - 1; t > 0; --t) {
        bool sw = (kd[t] < kd[t - 1]) ||
                  (kd[t] == kd[t - 1] && ki[t] < ki[t - 1]);
        if (sw) {
            float td = kd[t]; kd[t] = kd[t - 1]; kd[t - 1] = td;
            int ti = ki[t]; ki[t] = ki[t - 1]; ki[t - 1] = ti;
        }
    }
}

// ---------------- 1) squared norms ----------------
__global__ void sqnorm_kernel(const float* __restrict__ x) {
    int i = blockIdx.x * blockDim.x + threadIdx.x;
    const float4* xr = (const float4*)(x + (long)i * C_DIM);
    float s = 0.f;
#pragma unroll
    for (int t = 0; t < C_DIM / 4; ++t) {
        float4 v = xr[t];
        s += v.x * v.x + v.y * v.y + v.z * v.z + v.w * v.w;
    }
    g_sq[i] = s;
}

// ---------------- 2) tf32 hi/lo split of x ----------------
__global__ void split_kernel(const float* __restrict__ x) {
    int i = blockIdx.x * blockDim.x + threadIdx.x;   // uint4 index
    float4 v = ((const float4*)x)[i];
    uint4 h, l;
    h.x = tf32bits(v.x); l.x = tf32bits(v.x - __uint_as_float(h.x));
    h.y = tf32bits(v.y); l.y = tf32bits(v.y - __uint_as_float(h.y));
    h.z = tf32bits(v.z); l.z = tf32bits(v.z - __uint_as_float(h.z));
    h.w = tf32bits(v.w); l.w = tf32bits(v.w - __uint_as_float(h.w));
    g_hi4[i] = h; g_lo4[i] = l;
}

// ---------------- 3) feature GEMMs: A = x@(W1-W2)+b, B = x@W2 ----------------
__global__ void feat_gemm_kernel(const float* __restrict__ x,
                                 const float* __restrict__ W,
                                 const float* __restrict__ b) {
    __shared__ float xs[16][C_DIM];
    int col = threadIdx.x;
    int row0 = blockIdx.x * 16;
    ((float4*)xs)[col] = ((const float4*)(x + (long)row0 * C_DIM))[col];
    __syncthreads();

    float p1[16], p2[16];
#pragma unroll
    for (int r = 0; r < 16; ++r) { p1[r] = 0.f; p2[r] = 0.f; }
#pragma unroll 4
    for (int c = 0; c < C_DIM; ++c) {
        float w1 = __ldg(W + c * 256 + col);
        float w2 = __ldg(W + (C_DIM + c) * 256 + col);
#pragma unroll
        for (int r = 0; r < 16; ++r) {
            float xv = xs[r][c];
            p1[r] = fmaf(xv, w1, p1[r]);
            p2[r] = fmaf(xv, w2, p2[r]);
        }
    }
    float bias = __ldg(b + col);
#pragma unroll
    for (int r = 0; r < 16; ++r) {
        g_A[(long)(row0 + r) * 256 + col] = p1[r] - p2[r] + bias;
        g_B[(long)(row0 + r) * 256 + col] = p2[r];
    }
}

// ---------------- 4) KNN: 3xTF32 mma.sync -> smem dist tile -> row scan ----------------
__global__ void __launch_bounds__(NT, 1) knn_mma_kernel() {
    extern __shared__ float sm[];
    int tid = threadIdx.x;
    int warp = tid >> 5, lane = tid & 31;
    int g = lane >> 2, c = lane & 3;
    int qbase = blockIdx.x * QB;
    int r0 = (warp & 7) * 16;                 // warp's query m-stripe
    int nhalf = warp >> 3;                    // warp's n half (0: cols 0..31, 1: 32..63)

    // ---- fill query tiles (hi/lo, prescaled by -2; exact scaling) ----
#pragma unroll
    for (int it = 0; it < 4; ++it) {
        int idx = it * NT + tid;              // idx = q*16 + j
        int qq = idx >> 4, j = idx & 15;
        uint4 h = g_hi4[(long)(qbase + qq) * 16 + j];
        uint4 l = g_lo4[(long)(qbase + qq) * 16 + j];
        float4 fh, fl;
        fh.x = -2.f * __uint_as_float(h.x); fh.y = -2.f * __uint_as_float(h.y);
        fh.z = -2.f * __uint_as_float(h.z); fh.w = -2.f * __uint_as_float(h.w);
        fl.x = -2.f * __uint_as_float(l.x); fl.y = -2.f * __uint_as_float(l.y);
        fl.z = -2.f * __uint_as_float(l.z); fl.w = -2.f * __uint_as_float(l.w);
        *(float4*)&sm[OFF_QSH + qq * STR + j * 4] = fh;
        *(float4*)&sm[OFF_QSL + qq * STR + j * 4] = fl;
    }

    // db tile fill via cp.async
    auto fill_tile = [&](int tile, int buf) {
        int base = tile * DB;
        uint32_t dH = smem_u32(&sm[OFF_DB + buf * (2 * DB * STR)]);
        uint32_t dL = dH + DB * STR * 4;
        const uint4* sH = &g_hi4[(long)base * 16];
        const uint4* sL = &g_lo4[(long)base * 16];
#pragma unroll
        for (int it = 0; it < 2; ++it) {
            int idx = it * NT + tid;          // idx = n*16 + j, 1024 total
            int n = idx >> 4, j = idx & 15;
            uint32_t off = (uint32_t)(n * STR + j * 4) * 4;
            cp16(dH + off, sH + idx);
            cp16(dL + off, sL + idx);
        }
        if (tid < 16)
            cp16(smem_u32(&sm[OFF_SQD + buf * DB + tid * 4]), g_sq + base + tid * 4);
    };

    float kd[K_NN];
    int   ki[K_NN];
#pragma unroll
    for (int t = 0; t < K_NN; ++t) { kd[t] = CUDART_INF_F; ki[t] = 0x7fffffff; }

    fill_tile(0, 0);
    asm volatile("cp.async.commit_group;" ::: "memory");
    asm volatile("cp.async.wait_group 0;" ::: "memory");
    __syncthreads();

    for (int tile = 0; tile < NTILE; ++tile) {
        int buf = tile & 1;
        int tb = tile * DB;
        const float* dbH = &sm[OFF_DB + buf * (2 * DB * STR)];
        const float* dbL = dbH + DB * STR;
        const float* sq = &sm[OFF_SQD + buf * DB];

        // ---- phase A: mma (warp = m16 x n32), 16 warps cover 128q x 64db ----
        float acc[16];
#pragma unroll
        for (int i = 0; i < 16; ++i) acc[i] = 0.f;

#pragma unroll
        for (int kc = 0; kc < 8; ++kc) {
            int kb = kc * 8;
            const float* qh = &sm[OFF_QSH + (r0 + g) * STR + kb + c];
            const float* ql = &sm[OFF_QSL + (r0 + g) * STR + kb + c];
            uint32_t aH0 = *(const uint32_t*)(qh);
            uint32_t aH1 = *(const uint32_t*)(qh + 8 * STR);
            uint32_t aH2 = *(const uint32_t*)(qh + 4);
            uint32_t aH3 = *(const uint32_t*)(qh + 8 * STR + 4);
            uint32_t aL0 = *(const uint32_t*)(ql);
            uint32_t aL1 = *(const uint32_t*)(ql + 8 * STR);
            uint32_t aL2 = *(const uint32_t*)(ql + 4);
            uint32_t aL3 = *(const uint32_t*)(ql + 8 * STR + 4);
            const float* bh = dbH + (nhalf * 32 + g) * STR + kb + c;
            const float* bl = dbL + (nhalf * 32 + g) * STR + kb + c;
            uint32_t bH[4][2], bL[4][2];
#pragma unroll
            for (int nf = 0; nf < 4; ++nf) {
                bH[nf][0] = *(const uint32_t*)(bh + nf * 8 * STR);
                bH[nf][1] = *(const uint32_t*)(bh + nf * 8 * STR + 4);
                bL[nf][0] = *(const uint32_t*)(bl + nf * 8 * STR);
                bL[nf][1] = *(const uint32_t*)(bl + nf * 8 * STR + 4);
            }
            // term-major issue order: dependent MMAs are >=4 apart in program order
#pragma unroll
            for (int nf = 0; nf < 4; ++nf)
                mma_tf32(acc + nf * 4, aH0, aH1, aH2, aH3, bH[nf][0], bH[nf][1]);
#pragma unroll
            for (int nf = 0; nf < 4; ++nf)
                mma_tf32(acc + nf * 4, aL0, aL1, aL2, aL3, bH[nf][0], bH[nf][1]);
#pragma unroll
            for (int nf = 0; nf < 4; ++nf)
                mma_tf32(acc + nf * 4, aH0, aH1, aH2, aH3, bL[nf][0], bL[nf][1]);
        }
        // STS dist (+|p|^2; query norm dropped — rank-invariant)
#pragma unroll
        for (int nf = 0; nf < 4; ++nf) {
            int col0 = nhalf * 32 + nf * 8 + 2 * c;
            float2 s = *(const float2*)(sq + col0);
            float2 v0 = make_float2(acc[nf * 4 + 0] + s.x, acc[nf * 4 + 1] + s.y);
            float2 v1 = make_float2(acc[nf * 4 + 2] + s.x, acc[nf * 4 + 3] + s.y);
            *(float2*)&sm[OFF_DST + (r0 + g) * STR + col0] = v0;
            *(float2*)&sm[OFF_DST + (r0 + g + 8) * STR + col0] = v1;
        }

        // ---- prefetch next tile (overlaps the scan below) ----
        if (tile + 1 < NTILE) {
            fill_tile(tile + 1, buf ^ 1);
            asm volatile("cp.async.commit_group;" ::: "memory");
        }
        __syncthreads();   // dist tile ready

        // ---- phase B: scan (threads 0..127, one query each) ----
        if (tid < QB) {
            int q = qbase + tid;
            int self = q - tb;
            if ((unsigned)self < (unsigned)DB)
                sm[OFF_DST + tid * STR + self] = CUDART_INF_F;
            float thr = kd[K_NN - 1];
            const float* row = &sm[OFF_DST + tid * STR];
#pragma unroll
            for (int j = 0; j < DB / 4; ++j) {
                float4 dv = *(const float4*)(row + 4 * j);
                float mn = fminf(fminf(dv.x, dv.y), fminf(dv.z, dv.w));
                if (mn <= thr) {
                    float ds[4] = {dv.x, dv.y, dv.z, dv.w};
#pragma unroll
                    for (int e = 0; e < 4; ++e) {
                        int col = tb + 4 * j + e;
                        if (ds[e] < thr ||
                            (ds[e] == thr && col < ki[K_NN - 1])) {
                            ins_lex(ds[e], col, kd, ki);
                            thr = kd[K_NN - 1];
                        }
                    }
                }
            }
        }
        asm volatile("cp.async.wait_group 0;" ::: "memory");
        __syncthreads();   // next db buf ready + dist free
    }

    if (tid < QB) {
        int q = qbase + tid;
#pragma unroll
        for (int t = 0; t < K_NN; ++t) g_knn[(long)q * K_NN + t] = ki[t];
    }
}

// ---------------- 5) gather + max + relu + pixel-shuffle scatter ----------------
__global__ void gather_max_kernel(float* __restrict__ y) {
    int t = threadIdx.x;
    int q = blockIdx.x * 4 + (t >> 6);
    int c = t & 63;
    const int* idx = g_knn + (long)q * K_NN;
    const float4* Bv = (const float4*)g_B;
    float4 m = make_float4(-CUDART_INF_F, -CUDART_INF_F, -CUDART_INF_F, -CUDART_INF_F);
#pragma unroll
    for (int k = 0; k < K_NN; ++k) {
        int j = __ldg(idx + k);
        float4 bv = Bv[(long)j * 64 + c];
        m.x = fmaxf(m.x, bv.x); m.y = fmaxf(m.y, bv.y);
        m.z = fmaxf(m.z, bv.z); m.w = fmaxf(m.w, bv.w);
    }
    float4 a = ((const float4*)g_A)[(long)q * 64 + c];
    y[((long)q * 4 + 0) * 64 + c] = fmaxf(a.x + m.x, 0.f);
    y[((long)q * 4 + 1) * 64 + c] = fmaxf(a.y + m.y, 0.f);
    y[((long)q * 4 + 2) * 64 + c] = fmaxf(a.z + m.z, 0.f);
    y[((long)q * 4 + 3) * 64 + c] = fmaxf(a.w + m.w, 0.f);
}

extern "C" void kernel_launch(void* const* d_in, const int* in_sizes, int n_in,
                              void* d_out, int out_size) {
    const float* x = (const float*)d_in[0];   // (16384, 64) f32
    const float* W = (const float*)d_in[1];   // (128, 256) f32
    const float* b = (const float*)d_in[2];   // (256,) f32
    float* y = (float*)d_out;                 // (65536, 64) f32

    cudaFuncSetAttribute(knn_mma_kernel,
                         cudaFuncAttributeMaxDynamicSharedMemorySize, SMEM_DYN);

    sqnorm_kernel<<<N_PTS / 256, 256>>>(x);
    split_kernel<<<(N_PTS * C_DIM / 4) / 256, 256>>>(x);
    feat_gemm_kernel<<<N_PTS / 16, 256>>>(x, W, b);
    knn_mma_kernel<<<N_PTS / QB, NT, SMEM_DYN>>>();
    gather_max_kernel<<<N_PTS / 4, 256>>>(y);
}

// round 10
// speedup vs baseline: 4.9945x; 2.5874x over previous
#include <cuda_runtime.h>
#include <math_constants.h>
#include <cstdint>

#define N_PTS 16384
#define C_DIM 64
#define K_NN  16
#define QB    128
#define DBT   128
#define NTILE (N_PTS / DBT)     // 128
#define NT    512               // 16 warps
#define STRA  64                // A row stride (floats); broadcast reads, no conflicts
#define STRB  66                // B row stride; lane-strided reads conflict-free, 8B aligned
#define STRD  132               // dist row stride; 16B aligned

// smem offsets (floats)
#define OFF_A   0                              // 128*64   = 8192
#define OFF_B   8192                           // 2*128*66 = 16896
#define OFF_SQ  (8192 + 16896)                 // 25088 ; 2*128
#define OFF_DST 25344                          // 128*132 = 16896
#define OFF_TKD 42240                          // 16*128 kd (column layout)
#define OFF_TKI 44288                          // 16*128 ki
#define SMEM_FLOATS 46336
#define SMEM_DYN (SMEM_FLOATS * 4)             // 185344 bytes

// Scratch (device globals; no dynamic allocation allowed)
__device__ float g_sq[N_PTS];
__device__ int   g_knn[N_PTS * K_NN];
__device__ float g_A[N_PTS * 256];             // x@(W1-W2)+b
__device__ float g_B[N_PTS * 256];             // x@W2

// ---------------- helpers ----------------
static __device__ __forceinline__ uint32_t smem_u32(const void* p) {
    uint32_t a;
    asm("{ .reg .u64 t; cvta.to.shared.u64 t, %1; cvt.u32.u64 %0, t; }"
        : "=r"(a) : "l"(p));
    return a;
}
static __device__ __forceinline__ void cp8(uint32_t dst, const void* src) {
    asm volatile("cp.async.ca.shared.global [%0], [%1], 8;" :: "r"(dst), "l"(src));
}
// packed fp32x2 FMA, non-volatile so ptxas can schedule
static __device__ __forceinline__ void ffma2(unsigned long long& acc,
                                             unsigned long long a,
                                             unsigned long long b) {
    asm("fma.rn.f32x2 %0, %1, %2, %0;" : "+l"(acc) : "l"(a), "l"(b));
}

// ---------------- 1) squared norms ----------------
__global__ void sqnorm_kernel(const float* __restrict__ x) {
    int i = blockIdx.x * blockDim.x + threadIdx.x;
    const float4* xr = (const float4*)(x + (long)i * C_DIM);
    float s = 0.f;
#pragma unroll
    for (int t = 0; t < C_DIM / 4; ++t) {
        float4 v = xr[t];
        s += v.x * v.x + v.y * v.y + v.z * v.z + v.w * v.w;
    }
    g_sq[i] = s;
}

// ---------------- 2) feature GEMMs: A = x@(W1-W2)+b, B = x@W2 ----------------
__global__ void feat_gemm_kernel(const float* __restrict__ x,
                                 const float* __restrict__ W,
                                 const float* __restrict__ b) {
    __shared__ float xs[16][C_DIM];
    int col = threadIdx.x;
    int row0 = blockIdx.x * 16;
    ((float4*)xs)[col] = ((const float4*)(x + (long)row0 * C_DIM))[col];
    __syncthreads();

    float p1[16], p2[16];
#pragma unroll
    for (int r = 0; r < 16; ++r) { p1[r] = 0.f; p2[r] = 0.f; }
#pragma unroll 4
    for (int c = 0; c < C_DIM; ++c) {
        float w1 = __ldg(W + c * 256 + col);
        float w2 = __ldg(W + (C_DIM + c) * 256 + col);
#pragma unroll
        for (int r = 0; r < 16; ++r) {
            float xv = xs[r][c];
            p1[r] = fmaf(xv, w1, p1[r]);
            p2[r] = fmaf(xv, w2, p2[r]);
        }
    }
    float bias = __ldg(b + col);
#pragma unroll
    for (int r = 0; r < 16; ++r) {
        g_A[(long)(row0 + r) * 256 + col] = p1[r] - p2[r] + bias;
        g_B[(long)(row0 + r) * 256 + col] = p2[r];
    }
}

// ---------------- 3) KNN: f32x2 register-blocked SGEMM -> dist tile -> scan ----------------
__global__ void __launch_bounds__(NT, 1) knn_sgemm_kernel(const float* __restrict__ x) {
    extern __shared__ float sm[];
    int tid = threadIdx.x;
    int warp = tid >> 5, lane = tid & 31;
    int qbase = blockIdx.x * QB;
    int qg = warp;                       // warp owns queries qg*8 .. qg*8+7

    // ---- A tile fill: 128q x 64k, prescaled by -2 (exact scaling) ----
#pragma unroll
    for (int it = 0; it < 4; ++it) {
        int idx = it * NT + tid;         // 2048 float4
        int q = idx >> 4, j = idx & 15;
        float4 v = ((const float4*)(x + (long)(qbase + q) * C_DIM))[j];
        v.x *= -2.f; v.y *= -2.f; v.z *= -2.f; v.w *= -2.f;
        *(float4*)&sm[OFF_A + q * STRA + j * 4] = v;
    }

    // ---- top-k state in smem, column layout (stride QB: conflict-free) ----
    if (tid < QB) {
#pragma unroll
        for (int t = 0; t < K_NN; ++t) {
            sm[OFF_TKD + t * QB + tid] = CUDART_INF_F;
            ((int*)sm)[OFF_TKI + t * QB + tid] = 0x7fffffff;
        }
    }

    // ---- B tile fill via cp.async (8B; row stride 66 floats) ----
    auto fill_b = [&](int tile, int buf) {
        int base = tile * DBT;
        uint32_t bs = smem_u32(&sm[OFF_B + buf * (DBT * STRB)]);
        const float* src = x + (long)base * C_DIM;
#pragma unroll
        for (int it = 0; it < 8; ++it) {
            int idx = it * NT + tid;     // 4096 cp8: n = idx>>5, j = idx&31
            int n = idx >> 5, j = idx & 31;
            cp8(bs + (uint32_t)(n * STRB + j * 2) * 4, src + (long)n * C_DIM + j * 2);
        }
        if (tid < 64)
            cp8(smem_u32(&sm[OFF_SQ + buf * DBT]) + tid * 8, g_sq + base + tid * 2);
    };

    fill_b(0, 0);
    asm volatile("cp.async.commit_group;" ::: "memory");
    asm volatile("cp.async.wait_group 0;" ::: "memory");
    __syncthreads();

    for (int tile = 0; tile < NTILE; ++tile) {
        int buf = tile & 1;
        int tb = tile * DBT;
        const float* bb = &sm[OFF_B + buf * (DBT * STRB)];

        // ---- compute: thread = 8q x 4db, f32x2 packed over k ----
        unsigned long long acc[8][4];
#pragma unroll
        for (int i = 0; i < 8; ++i)
#pragma unroll
            for (int m = 0; m < 4; ++m) acc[i][m] = 0ull;

#pragma unroll
        for (int kk = 0; kk < C_DIM / 4; ++kk) {
            unsigned long long b0[4], b1[4];
#pragma unroll
            for (int m = 0; m < 4; ++m) {
                const float* bp = bb + (lane + 32 * m) * STRB + kk * 4;
                b0[m] = *(const unsigned long long*)(bp);
                b1[m] = *(const unsigned long long*)(bp + 2);
            }
#pragma unroll
            for (int qh = 0; qh < 2; ++qh) {
                ulonglong2 a[4];
#pragma unroll
                for (int i = 0; i < 4; ++i)
                    a[i] = *(const ulonglong2*)&sm[OFF_A + (qg * 8 + qh * 4 + i) * STRA + kk * 4];
#pragma unroll
                for (int i = 0; i < 4; ++i)
#pragma unroll
                    for (int m = 0; m < 4; ++m)
                        ffma2(acc[qh * 4 + i][m], a[i].x, b0[m]);
#pragma unroll
                for (int i = 0; i < 4; ++i)
#pragma unroll
                    for (int m = 0; m < 4; ++m)
                        ffma2(acc[qh * 4 + i][m], a[i].y, b1[m]);
            }
        }

        // ---- prefetch next B tile (overlaps epilogue + scan) ----
        if (tile + 1 < NTILE) {
            fill_b(tile + 1, buf ^ 1);
            asm volatile("cp.async.commit_group;" ::: "memory");
        }

        // ---- epilogue: d = sum2(acc) + |p|^2 (query norm dropped) ----
        {
            float sqv[4];
#pragma unroll
            for (int m = 0; m < 4; ++m) sqv[m] = sm[OFF_SQ + buf * DBT + lane + 32 * m];
#pragma unroll
            for (int i = 0; i < 8; ++i) {
#pragma unroll
                for (int m = 0; m < 4; ++m) {
                    float lo = __uint_as_float((uint32_t)acc[i][m]);
                    float hi = __uint_as_float((uint32_t)(acc[i][m] >> 32));
                    sm[OFF_DST + (qg * 8 + i) * STRD + lane + 32 * m] = lo + hi + sqv[m];
                }
            }
        }
        __syncthreads();   // dist tile ready

        // ---- scan: threads 0..127, one query each; top-k in smem ----
        if (tid < QB) {
            int q = qbase + tid;
            int self = q - tb;
            if ((unsigned)self < (unsigned)DBT)
                sm[OFF_DST + tid * STRD + self] = CUDART_INF_F;
            float* kds = &sm[OFF_TKD + tid];
            int* kis = ((int*)sm) + OFF_TKI + tid;
            float thr = kds[15 * QB];
            int thi = kis[15 * QB];
            const float* row = &sm[OFF_DST + tid * STRD];
#pragma unroll 4
            for (int j = 0; j < DBT / 4; ++j) {
                float4 dv = *(const float4*)(row + 4 * j);
                float mn = fminf(fminf(dv.x, dv.y), fminf(dv.z, dv.w));
                if (mn <= thr) {
                    float ds[4] = {dv.x, dv.y, dv.z, dv.w};
#pragma unroll
                    for (int e = 0; e < 4; ++e) {
                        float d = ds[e];
                        int col = tb + 4 * j + e;
                        if (d < thr || (d == thr && col < thi)) {
                            // smem insertion sort (cold path)
                            kds[15 * QB] = d; kis[15 * QB] = col;
#pragma unroll
                            for (int t = K_NN - 1; t > 0; --t) {
                                float da = kds[t * QB], db_ = kds[(t - 1) * QB];
                                int ia = kis[t * QB], ib = kis[(t - 1) * QB];
                                if (da < db_ || (da == db_ && ia < ib)) {
                                    kds[t * QB] = db_; kds[(t - 1) * QB] = da;
                                    kis[t * QB] = ib;  kis[(t - 1) * QB] = ia;
                                }
                            }
                            thr = kds[15 * QB];
                            thi = kis[15 * QB];
                        }
                    }
                }
            }
        }
        asm volatile("cp.async.wait_group 0;" ::: "memory");
        __syncthreads();   // next B buf ready + dist free
    }

    if (tid < QB) {
        int q = qbase + tid;
#pragma unroll
        for (int t = 0; t < K_NN; ++t)
            g_knn[(long)q * K_NN + t] = ((int*)sm)[OFF_TKI + t * QB + tid];
    }
}

// ---------------- 4) gather + max + relu + pixel-shuffle scatter ----------------
__global__ void gather_max_kernel(float* __restrict__ y) {
    int t = threadIdx.x;
    int q = blockIdx.x * 4 + (t >> 6);
    int c = t & 63;
    const int* idx = g_knn + (long)q * K_NN;
    const float4* Bv = (const float4*)g_B;
    float4 m = make_float4(-CUDART_INF_F, -CUDART_INF_F, -CUDART_INF_F, -CUDART_INF_F);
#pragma unroll
    for (int k = 0; k < K_NN; ++k) {
        int j = __ldg(idx + k);
        float4 bv = Bv[(long)j * 64 + c];
        m.x = fmaxf(m.x, bv.x); m.y = fmaxf(m.y, bv.y);
        m.z = fmaxf(m.z, bv.z); m.w = fmaxf(m.w, bv.w);
    }
    float4 a = ((const float4*)g_A)[(long)q * 64 + c];
    y[((long)q * 4 + 0) * 64 + c] = fmaxf(a.x + m.x, 0.f);
    y[((long)q * 4 + 1) * 64 + c] = fmaxf(a.y + m.y, 0.f);
    y[((long)q * 4 + 2) * 64 + c] = fmaxf(a.z + m.z, 0.f);
    y[((long)q * 4 + 3) * 64 + c] = fmaxf(a.w + m.w, 0.f);
}

extern "C" void kernel_launch(void* const* d_in, const int* in_sizes, int n_in,
                              void* d_out, int out_size) {
    const float* x = (const float*)d_in[0];   // (16384, 64) f32
    const float* W = (const float*)d_in[1];   // (128, 256) f32
    const float* b = (const float*)d_in[2];   // (256,) f32
    float* y = (float*)d_out;                 // (65536, 64) f32

    cudaFuncSetAttribute(knn_sgemm_kernel,
                         cudaFuncAttributeMaxDynamicSharedMemorySize, SMEM_DYN);

    sqnorm_kernel<<<N_PTS / 256, 256>>>(x);
    feat_gemm_kernel<<<N_PTS / 16, 256>>>(x, W, b);
    knn_sgemm_kernel<<<N_PTS / QB, NT, SMEM_DYN>>>(x);
    gather_max_kernel<<<N_PTS / 4, 256>>>(y);
}